// round 11
// baseline (speedup 1.0000x reference)
#include <cuda_runtime.h>
#include <cuda_fp16.h>
#include <cstdint>

// ---------------------------------------------------------------- problem dims
#define NDIRS   6
#define IDIM_   256
#define ODIM_   512
#define LSEQ    4096
#define NCHN    8192
#define NTOK    32768
#define KTOT    512
#define MTILE   128
#define KC      32                    // K per smem chunk
#define NKCH    16                    // K chunks per unit (K=512)
#define NNB     4                     // n-blocks of 128
#define NCG     (NNB * NKCH)          // 64 B-blocks per dir-tile
#define NWORKERS 296                  // 2 CTAs per SM x 148 SMs

// B packed block (fp16): per (dir, cg): 2 kk16-groups * 4 tig * 1056B rows
#define BROW_BYTES   1056             // 128 cols * 8B + 32B pad
#define BBLK_BYTES   (2 * 4 * BROW_BYTES)   // 8448
#define BUNITS       (BBLK_BYTES / 16)      // 528 16B units

// A smem (fp16): 128 rows * 40 halfs (80B stride; 64B data)
#define A_STRIDEH    40
#define A_BYTES      (128 * A_STRIDEH * 2)  // 10240
#define STAGE_BYTES  (A_BYTES + BBLK_BYTES) // 18688
#define SM_ROWTOK    0
#define SM_ROWS0     512
#define SM_ROWS1     1024
#define SM_UNIT      1536
#define SM_STAGE     2048
#define SMEM_DYN     (SM_STAGE + 2 * STAGE_BYTES)   // 39424

// ---------------------------------------------------------------- device scratch
__device__ __align__(16) char g_WpH[NDIRS * NCG * BBLK_BYTES];  // fp16 fragment-packed W
__device__ int   g_count[NDIRS];
__device__ int   g_work;
__device__ int2  g_bucket[NDIRS * NTOK];

// ---------------------------------------------------------------- helpers
__device__ __forceinline__ uint32_t smem_u32(const void* p) {
    uint32_t a;
    asm("{ .reg .u64 t; cvta.to.shared.u64 t, %1; cvt.u32.u64 %0, t; }" : "=r"(a) : "l"(p));
    return a;
}
__device__ __forceinline__ void cp16(uint32_t dst, const void* src) {
    asm volatile("cp.async.cg.shared.global [%0], [%1], 16;\n" :: "r"(dst), "l"(src) : "memory");
}
#define CP_COMMIT() asm volatile("cp.async.commit_group;\n" ::: "memory")
#define CP_WAIT0()  asm volatile("cp.async.wait_group 0;\n" ::: "memory")

__device__ __forceinline__ void mma16(float* c, const uint32_t* a, const uint32_t* b) {
    asm volatile(
        "mma.sync.aligned.m16n8k16.row.col.f32.f16.f16.f32 "
        "{%0,%1,%2,%3}, {%4,%5,%6,%7}, {%8,%9}, {%0,%1,%2,%3};\n"
        : "+f"(c[0]), "+f"(c[1]), "+f"(c[2]), "+f"(c[3])
        : "r"(a[0]), "r"(a[1]), "r"(a[2]), "r"(a[3]), "r"(b[0]), "r"(b[1]));
}

__device__ __forceinline__ uint32_t pack_h2(float a, float b) {
    __half2 h = __floats2half2_rn(a, b);
    return *(uint32_t*)&h;
}

// ---------------------------------------------------------------- K0: pack W -> fp16 fragment layout
__global__ void k_prep(const float* __restrict__ W) {
    if (blockIdx.x == 0 && threadIdx.x < NDIRS + 1) {
        if (threadIdx.x < NDIRS) g_count[threadIdx.x] = 0;
        else g_work = 0;
    }
    int linear = blockIdx.x * 256 + threadIdx.x;
    int col = linear & 127;
    int kk  = (linear >> 7) & 1;
    int ch  = (linear >> 8) & 15;
    int nbd = linear >> 12;                      // d*4 + nb, 0..23

    const float* src = W + ((size_t)nbd * 128 + col) * KTOT + ch * KC + kk * 16;
    float x[16];
    #pragma unroll
    for (int i = 0; i < 4; i++) {
        float4 v = *(const float4*)(src + i * 4);
        x[i * 4 + 0] = v.x; x[i * 4 + 1] = v.y; x[i * 4 + 2] = v.z; x[i * 4 + 3] = v.w;
    }
    char* dst = g_WpH + (size_t)(nbd * 16 + ch) * BBLK_BYTES + kk * (4 * BROW_BYTES) + col * 8;
    #pragma unroll
    for (int t = 0; t < 4; t++) {
        uint2 u;
        u.x = pack_h2(x[2 * t],     x[2 * t + 1]);
        u.y = pack_h2(x[8 + 2 * t], x[9 + 2 * t]);
        *(uint2*)(dst + t * BROW_BYTES) = u;
    }
}

// ---------------------------------------------------------------- K1: bucket tokens by dir
__global__ void k_bucket(const int* __restrict__ child_l, const int* __restrict__ child_r,
                         const int* __restrict__ vec, const int* __restrict__ drev,
                         const int* __restrict__ dmap) {
    int t = blockIdx.x * blockDim.x + threadIdx.x;
    int l = t & (LSEQ - 1);
    int v = vec[t];
    int dir = dmap[v];
    int d = drev[v];
    int cl = child_l[l], cr = child_r[l];
    int c0 = d ? cr : cl;
    int c1 = d ? cl : cr;
    int payload = c0 | (c1 << 16);
    int lane = threadIdx.x & 31;

    #pragma unroll
    for (int dd = 0; dd < NDIRS; dd++) {
        unsigned mask = __ballot_sync(0xFFFFFFFFu, dir == dd);
        if (dir == dd) {
            int leader = __ffs(mask) - 1;
            int base = 0;
            if (lane == leader) base = atomicAdd(&g_count[dd], __popc(mask));
            base = __shfl_sync(mask, base, leader);
            int pos = base + __popc(mask & ((1u << lane) - 1u));
            g_bucket[dd * NTOK + pos] = make_int2(t, payload);
        }
    }
}

// ---------------------------------------------------------------- K2: persistent bucketed fp16 GEMM
// 296 persistent CTAs, dynamic queue over units = (dir-tile, nb): 128x128x512 each.
__global__ void __launch_bounds__(128, 2) k_gemm(
    const float* __restrict__ last,
    const float* __restrict__ b_merge,
    const float* __restrict__ alpha_merge,
    float* __restrict__ out)
{
    extern __shared__ char smp[];
    const uint32_t sbase = smem_u32(smp);

    const int tid = threadIdx.x;
    const int wid = tid >> 5;
    const int lid = tid & 31;
    const int wm = wid & 1;       // M half (64 rows)
    const int wn = wid >> 1;      // N half (64 cols)
    const int g   = lid >> 2;     // group (0..7)
    const int tig = lid & 3;      // thread-in-group (0..3)

    // ---- per-dir tile prefix
    int pref[NDIRS + 1];
    pref[0] = 0;
    #pragma unroll
    for (int d = 0; d < NDIRS; d++)
        pref[d + 1] = pref[d] + ((g_count[d] + MTILE - 1) >> 7);
    const int totalUnits = pref[NDIRS] * NNB;

    const int* rs0 = (const int*)(smp + SM_ROWS0);
    const int* rs1 = (const int*)(smp + SM_ROWS1);
    const int* rowTok = (const int*)(smp + SM_ROWTOK);

    for (;;) {
        // ---- grab next unit
        if (tid == 0) *(int*)(smp + SM_UNIT) = atomicAdd(&g_work, 1);
        __syncthreads();
        const int u = *(int*)(smp + SM_UNIT);
        __syncthreads();
        if (u >= totalUnits) break;

        const int T = u >> 2;           // dir-tile
        const int nb = u & 3;
        int dir = 0;
        #pragma unroll
        for (int d = 1; d < NDIRS; d++) if (T >= pref[d]) dir = d;
        const int tile = T - pref[dir];
        const int count = g_count[dir];

        // ---- row metadata (128 threads cover 128 rows)
        {
            int idx = tile * MTILE + tid;
            int2 e = (idx < count) ? g_bucket[dir * NTOK + idx] : make_int2(0, 0);
            ((int*)(smp + SM_ROWTOK))[tid] = (idx < count) ? e.x : -1;
            int c0 = e.y & 0xFFFF;
            int c1 = (e.y >> 16) & 0xFFFF;
            int bb = e.x >> 12;
            ((int*)(smp + SM_ROWS0))[tid] = bb * NCHN + c0;
            ((int*)(smp + SM_ROWS1))[tid] = bb * NCHN + c1;
        }
        const float alpha = alpha_merge[dir];
        __syncthreads();

        const char* __restrict__ WpB = g_WpH + (size_t)(dir * NCG + nb * NKCH) * BBLK_BYTES;

        float acc[4][8][4];
        #pragma unroll
        for (int t = 0; t < 4; t++)
            #pragma unroll
            for (int j = 0; j < 8; j++)
                #pragma unroll
                for (int q = 0; q < 4; q++) acc[t][j][q] = 0.f;

        // ---- prologue: fill chunk 0 into stage 0
        {
            uint32_t bdst = sbase + SM_STAGE + A_BYTES;
            const char* bsrc = WpB;
            #pragma unroll
            for (int i = 0; i < 4; i++) { int v = tid + i * 128; cp16(bdst + v * 16, bsrc + v * 16); }
            if (tid < BUNITS - 512) { int v = tid + 512; cp16(bdst + v * 16, bsrc + v * 16); }
            CP_COMMIT();
            __half* adst = (__half*)(smp + SM_STAGE);
            #pragma unroll
            for (int i = 0; i < 4; i++) {
                int v = tid + i * 128;
                int row = v >> 2, q = v & 3;
                const float* ap = last + (size_t)rs0[row] * IDIM_ + q * 8;
                float4 v0 = *(const float4*)(ap);
                float4 v1 = *(const float4*)(ap + 4);
                uint4 h;
                h.x = pack_h2(v0.x, v0.y); h.y = pack_h2(v0.z, v0.w);
                h.z = pack_h2(v1.x, v1.y); h.w = pack_h2(v1.z, v1.w);
                *(uint4*)(adst + row * A_STRIDEH + q * 8) = h;
            }
            CP_WAIT0();
            __syncthreads();
        }

        for (int c = 0; c < NKCH; c++) {
            const int s = c & 1;
            float4 apf[8];

            // ---- prefetch chunk c+1: B via cp.async, A via LDG (held in regs)
            if (c < NKCH - 1) {
                const int c2 = c + 1;
                uint32_t bdst = sbase + SM_STAGE + (s ^ 1) * STAGE_BYTES + A_BYTES;
                const char* bsrc = WpB + (size_t)c2 * BBLK_BYTES;
                #pragma unroll
                for (int i = 0; i < 4; i++) { int v = tid + i * 128; cp16(bdst + v * 16, bsrc + v * 16); }
                if (tid < BUNITS - 512) { int v = tid + 512; cp16(bdst + v * 16, bsrc + v * 16); }
                CP_COMMIT();
                const int* rs = (c2 < 8) ? rs0 : rs1;
                const int koff = (c2 & 7) * KC;
                #pragma unroll
                for (int i = 0; i < 4; i++) {
                    int v = tid + i * 128;
                    int row = v >> 2, q = v & 3;
                    const float* ap = last + (size_t)rs[row] * IDIM_ + koff + q * 8;
                    apf[2 * i]     = *(const float4*)(ap);
                    apf[2 * i + 1] = *(const float4*)(ap + 4);
                }
            }

            // ---- compute chunk c from stage s
            const __half* As = (const __half*)(smp + SM_STAGE + s * STAGE_BYTES);
            const char*   Bs = smp + SM_STAGE + s * STAGE_BYTES + A_BYTES;
            #pragma unroll
            for (int kk = 0; kk < 2; kk++) {
                uint32_t af[4][4];
                uint32_t bf[8][2];
                #pragma unroll
                for (int t = 0; t < 4; t++) {
                    const __half* p = As + (wm * 64 + t * 16 + g) * A_STRIDEH + kk * 16 + 2 * tig;
                    af[t][0] = *(const uint32_t*)(p);
                    af[t][1] = *(const uint32_t*)(p + 8 * A_STRIDEH);
                    af[t][2] = *(const uint32_t*)(p + 8);
                    af[t][3] = *(const uint32_t*)(p + 8 * A_STRIDEH + 8);
                }
                #pragma unroll
                for (int j = 0; j < 8; j++) {
                    uint2 v = *(const uint2*)(Bs + kk * (4 * BROW_BYTES) + tig * BROW_BYTES
                                              + (wn * 64 + j * 8 + g) * 8);
                    bf[j][0] = v.x;
                    bf[j][1] = v.y;
                }
                #pragma unroll
                for (int t = 0; t < 4; t++)
                    #pragma unroll
                    for (int j = 0; j < 8; j++)
                        mma16(acc[t][j], af[t], bf[j]);
            }

            // ---- convert + store prefetched A into the other stage
            if (c < NKCH - 1) {
                __half* adst = (__half*)(smp + SM_STAGE + (s ^ 1) * STAGE_BYTES);
                #pragma unroll
                for (int i = 0; i < 4; i++) {
                    int v = tid + i * 128;
                    int row = v >> 2, q = v & 3;
                    uint4 h;
                    h.x = pack_h2(apf[2 * i].x,     apf[2 * i].y);
                    h.y = pack_h2(apf[2 * i].z,     apf[2 * i].w);
                    h.z = pack_h2(apf[2 * i + 1].x, apf[2 * i + 1].y);
                    h.w = pack_h2(apf[2 * i + 1].z, apf[2 * i + 1].w);
                    *(uint4*)(adst + row * A_STRIDEH + q * 8) = h;
                }
                CP_WAIT0();
                __syncthreads();
            }
        }

        // ---- epilogue for this unit
        {
            const float* bm = b_merge + dir * ODIM_ + nb * 128 + wn * 64;
            float2 bb[8];
            #pragma unroll
            for (int j = 0; j < 8; j++) bb[j] = *(const float2*)(bm + j * 8 + 2 * tig);
            #pragma unroll
            for (int t = 0; t < 4; t++) {
                #pragma unroll
                for (int h = 0; h < 2; h++) {
                    int r = wm * 64 + t * 16 + h * 8 + g;
                    int tok = rowTok[r];
                    if (tok >= 0) {
                        float* op = out + (size_t)tok * ODIM_ + nb * 128 + wn * 64;
                        #pragma unroll
                        for (int j = 0; j < 8; j++) {
                            float y0 = acc[t][j][h * 2 + 0] + bb[j].x;
                            float y1 = acc[t][j][h * 2 + 1] + bb[j].y;
                            float2 v;
                            v.x = y0 > 0.f ? y0 : alpha * y0;
                            v.y = y1 > 0.f ? y1 : alpha * y1;
                            *(float2*)(op + j * 8 + 2 * tig) = v;
                        }
                    }
                }
            }
        }
        __syncthreads();   // metadata arrays reused by next unit
    }
}

// ---------------------------------------------------------------- launch
extern "C" void kernel_launch(void* const* d_in, const int* in_sizes, int n_in,
                              void* d_out, int out_size) {
    const float* last  = (const float*)d_in[0];
    const float* W     = (const float*)d_in[1];
    const float* bm    = (const float*)d_in[2];
    const float* am    = (const float*)d_in[3];
    const int*   cl    = (const int*)d_in[4];
    const int*   cr    = (const int*)d_in[5];
    const int*   vec   = (const int*)d_in[6];
    const int*   drev  = (const int*)d_in[7];
    const int*   dmap  = (const int*)d_in[8];
    float*       out   = (float*)d_out;

    (void)in_sizes; (void)n_in; (void)out_size;

    static bool attr_done = false;
    if (!attr_done) {
        cudaFuncSetAttribute(k_gemm, cudaFuncAttributeMaxDynamicSharedMemorySize, SMEM_DYN);
        attr_done = true;
    }

    k_prep<<<384, 256>>>(W);
    k_bucket<<<NTOK / 256, 256>>>(cl, cr, vec, drev, dmap);
    k_gemm<<<NWORKERS, 128, SMEM_DYN>>>(last, bm, am, out);
}

// round 12
// speedup vs baseline: 1.2687x; 1.2687x over previous
#include <cuda_runtime.h>
#include <cuda_fp16.h>
#include <cstdint>

// ---------------------------------------------------------------- problem dims
#define NDIRS   6
#define IDIM_   256
#define ODIM_   512
#define LSEQ    4096
#define NCHN    8192
#define NTOK    32768
#define KTOT    512
#define MTILE   256                   // CTA M tile (8 warps, m64 x n64 each)
#define KC      32                    // K per smem chunk
#define NKCH    16                    // K chunks per n-block
#define NNB     4                     // n-blocks of 128
#define NCG     (NNB * NKCH)          // 64 global chunks
#define MAXTILES (NTOK / MTILE + NDIRS)   // 134

// B packed block (fp16): per (dir, cg): 2 kk16-groups * 4 tig * 1056B rows
#define BROW_BYTES   1056             // 128 cols * 8B + 32B pad
#define BBLK_BYTES   (2 * 4 * BROW_BYTES)   // 8448
#define BUNITS       (BBLK_BYTES / 16)      // 528 16B units

// A smem (fp16): 256 rows * 40 halfs (80B stride; 64B data)
#define A_STRIDEH    40
#define A_BYTES      (256 * A_STRIDEH * 2)  // 20480
#define STAGE_BYTES  (A_BYTES + BBLK_BYTES) // 28928
#define SM_ROWTOK    0
#define SM_ROWS0     1024
#define SM_ROWS1     2048
#define SM_STAGE     3072
#define SMEM_DYN     (SM_STAGE + 2 * STAGE_BYTES)   // 60928

// ---------------------------------------------------------------- device scratch
__device__ __align__(16) char g_WpH[NDIRS * NCG * BBLK_BYTES];  // fp16 fragment-packed W
__device__ int   g_count[NDIRS];
__device__ int2  g_bucket[NDIRS * NTOK];

// ---------------------------------------------------------------- helpers
__device__ __forceinline__ uint32_t smem_u32(const void* p) {
    uint32_t a;
    asm("{ .reg .u64 t; cvta.to.shared.u64 t, %1; cvt.u32.u64 %0, t; }" : "=r"(a) : "l"(p));
    return a;
}
__device__ __forceinline__ void cp16(uint32_t dst, const void* src) {
    asm volatile("cp.async.cg.shared.global [%0], [%1], 16;\n" :: "r"(dst), "l"(src) : "memory");
}
#define CP_COMMIT() asm volatile("cp.async.commit_group;\n" ::: "memory")
#define CP_WAIT0()  asm volatile("cp.async.wait_group 0;\n" ::: "memory")

__device__ __forceinline__ void mma16(float* c, const uint32_t* a, const uint32_t* b) {
    asm volatile(
        "mma.sync.aligned.m16n8k16.row.col.f32.f16.f16.f32 "
        "{%0,%1,%2,%3}, {%4,%5,%6,%7}, {%8,%9}, {%0,%1,%2,%3};\n"
        : "+f"(c[0]), "+f"(c[1]), "+f"(c[2]), "+f"(c[3])
        : "r"(a[0]), "r"(a[1]), "r"(a[2]), "r"(a[3]), "r"(b[0]), "r"(b[1]));
}

__device__ __forceinline__ uint32_t pack_h2(float a, float b) {
    __half2 h = __floats2half2_rn(a, b);
    return *(uint32_t*)&h;
}

// ---------------------------------------------------------------- K0: pack W -> fp16 fragment layout
__global__ void k_prep(const float* __restrict__ W) {
    if (blockIdx.x == 0 && threadIdx.x < NDIRS) g_count[threadIdx.x] = 0;
    int linear = blockIdx.x * 256 + threadIdx.x;
    int col = linear & 127;
    int kk  = (linear >> 7) & 1;
    int ch  = (linear >> 8) & 15;
    int nbd = linear >> 12;                      // d*4 + nb, 0..23

    const float* src = W + ((size_t)nbd * 128 + col) * KTOT + ch * KC + kk * 16;
    float x[16];
    #pragma unroll
    for (int i = 0; i < 4; i++) {
        float4 v = *(const float4*)(src + i * 4);
        x[i * 4 + 0] = v.x; x[i * 4 + 1] = v.y; x[i * 4 + 2] = v.z; x[i * 4 + 3] = v.w;
    }
    char* dst = g_WpH + (size_t)(nbd * 16 + ch) * BBLK_BYTES + kk * (4 * BROW_BYTES) + col * 8;
    #pragma unroll
    for (int t = 0; t < 4; t++) {
        uint2 u;
        u.x = pack_h2(x[2 * t],     x[2 * t + 1]);
        u.y = pack_h2(x[8 + 2 * t], x[9 + 2 * t]);
        *(uint2*)(dst + t * BROW_BYTES) = u;
    }
}

// ---------------------------------------------------------------- K1: bucket tokens by dir
__global__ void k_bucket(const int* __restrict__ child_l, const int* __restrict__ child_r,
                         const int* __restrict__ vec, const int* __restrict__ drev,
                         const int* __restrict__ dmap) {
    int t = blockIdx.x * blockDim.x + threadIdx.x;
    int l = t & (LSEQ - 1);
    int v = vec[t];
    int dir = dmap[v];
    int d = drev[v];
    int cl = child_l[l], cr = child_r[l];
    int c0 = d ? cr : cl;
    int c1 = d ? cl : cr;
    int payload = c0 | (c1 << 16);
    int lane = threadIdx.x & 31;

    #pragma unroll
    for (int dd = 0; dd < NDIRS; dd++) {
        unsigned mask = __ballot_sync(0xFFFFFFFFu, dir == dd);
        if (dir == dd) {
            int leader = __ffs(mask) - 1;
            int base = 0;
            if (lane == leader) base = atomicAdd(&g_count[dd], __popc(mask));
            base = __shfl_sync(mask, base, leader);
            int pos = base + __popc(mask & ((1u << lane) - 1u));
            g_bucket[dd * NTOK + pos] = make_int2(t, payload);
        }
    }
}

// ---------------------------------------------------------------- K2: bucketed fp16 GEMM, M=256 CTA, 1 wave
// 256 threads = 8 warps. Warp tile m64 x n64: wm = wid&3 (M quarter), wn = wid>>2 (N half).
__global__ void __launch_bounds__(256, 1) k_gemm(
    const float* __restrict__ last,
    const float* __restrict__ b_merge,
    const float* __restrict__ alpha_merge,
    float* __restrict__ out)
{
    extern __shared__ char smp[];
    const uint32_t sbase = smem_u32(smp);

    const int tid = threadIdx.x;
    const int wid = tid >> 5;
    const int lid = tid & 31;
    const int wm = wid & 3;       // M quarter (64 rows)
    const int wn = wid >> 2;      // N half (64 cols)
    const int g   = lid >> 2;     // group (0..7)
    const int tig = lid & 3;      // thread-in-group (0..3)

    // ---- map CTA -> (dir, tile)
    int dir = -1, tile = 0;
    {
        int acc0 = 0;
        #pragma unroll
        for (int d = 0; d < NDIRS; d++) {
            int nt = (g_count[d] + MTILE - 1) >> 8;
            if (dir < 0 && (int)blockIdx.x < acc0 + nt) { dir = d; tile = blockIdx.x - acc0; }
            acc0 += nt;
        }
    }
    if (dir < 0) return;
    const int count = g_count[dir];
    const int rowbase = tile * MTILE;

    // ---- row metadata (256 threads cover 256 rows)
    {
        int idx = rowbase + tid;
        int2 e = (idx < count) ? g_bucket[dir * NTOK + idx] : make_int2(0, 0);
        ((int*)(smp + SM_ROWTOK))[tid] = (idx < count) ? e.x : -1;
        int c0 = e.y & 0xFFFF;
        int c1 = (e.y >> 16) & 0xFFFF;
        int bb = e.x >> 12;                 // token / LSEQ
        ((int*)(smp + SM_ROWS0))[tid] = bb * NCHN + c0;
        ((int*)(smp + SM_ROWS1))[tid] = bb * NCHN + c1;
    }
    const float alpha = alpha_merge[dir];
    __syncthreads();

    const int* rs0 = (const int*)(smp + SM_ROWS0);
    const int* rs1 = (const int*)(smp + SM_ROWS1);
    const int* rowTok = (const int*)(smp + SM_ROWTOK);
    const char* __restrict__ WpB = g_WpH + (size_t)(dir * NCG) * BBLK_BYTES;

    float acc[4][8][4];
    #pragma unroll
    for (int t = 0; t < 4; t++)
        #pragma unroll
        for (int j = 0; j < 8; j++)
            #pragma unroll
            for (int q = 0; q < 4; q++) acc[t][j][q] = 0.f;

    // ---- prologue: fill chunk 0 into stage 0
    {
        uint32_t bdst = sbase + SM_STAGE + A_BYTES;
        const char* bsrc = WpB;
        #pragma unroll
        for (int i = 0; i < 2; i++) { int u = tid + i * 256; cp16(bdst + u * 16, bsrc + u * 16); }
        if (tid < BUNITS - 512) { int u = tid + 512; cp16(bdst + u * 16, bsrc + u * 16); }
        CP_COMMIT();
        __half* adst = (__half*)(smp + SM_STAGE);
        #pragma unroll
        for (int i = 0; i < 4; i++) {
            int u = tid + i * 256;            // 1024 units: 256 rows x 4 eight-half groups
            int row = u >> 2, q = u & 3;
            const float* ap = last + (size_t)rs0[row] * IDIM_ + q * 8;
            float4 v0 = *(const float4*)(ap);
            float4 v1 = *(const float4*)(ap + 4);
            uint4 h;
            h.x = pack_h2(v0.x, v0.y); h.y = pack_h2(v0.z, v0.w);
            h.z = pack_h2(v1.x, v1.y); h.w = pack_h2(v1.z, v1.w);
            *(uint4*)(adst + row * A_STRIDEH + q * 8) = h;
        }
        CP_WAIT0();
        __syncthreads();
    }

    for (int cg = 0; cg < NCG; cg++) {
        const int s = cg & 1;
        float4 apf[8];

        // ---- prefetch chunk cg+1: B via cp.async, A via LDG (held in regs)
        if (cg < NCG - 1) {
            const int c2 = cg + 1;
            uint32_t bdst = sbase + SM_STAGE + (s ^ 1) * STAGE_BYTES + A_BYTES;
            const char* bsrc = WpB + (size_t)c2 * BBLK_BYTES;
            #pragma unroll
            for (int i = 0; i < 2; i++) { int u = tid + i * 256; cp16(bdst + u * 16, bsrc + u * 16); }
            if (tid < BUNITS - 512) { int u = tid + 512; cp16(bdst + u * 16, bsrc + u * 16); }
            CP_COMMIT();
            const int* rs = ((c2 & 15) < 8) ? rs0 : rs1;
            const int koff = (c2 & 7) * KC;
            #pragma unroll
            for (int i = 0; i < 4; i++) {
                int u = tid + i * 256;
                int row = u >> 2, q = u & 3;
                const float* ap = last + (size_t)rs[row] * IDIM_ + koff + q * 8;
                apf[2 * i]     = *(const float4*)(ap);
                apf[2 * i + 1] = *(const float4*)(ap + 4);
            }
        }

        // ---- compute chunk cg from stage s (2 k16-groups x 32 MMA per warp)
        const __half* As = (const __half*)(smp + SM_STAGE + s * STAGE_BYTES);
        const char*   Bs = smp + SM_STAGE + s * STAGE_BYTES + A_BYTES;
        #pragma unroll
        for (int kk = 0; kk < 2; kk++) {
            uint32_t af[4][4];
            uint32_t bf[8][2];
            #pragma unroll
            for (int t = 0; t < 4; t++) {
                const __half* p = As + (wm * 64 + t * 16 + g) * A_STRIDEH + kk * 16 + 2 * tig;
                af[t][0] = *(const uint32_t*)(p);
                af[t][1] = *(const uint32_t*)(p + 8 * A_STRIDEH);
                af[t][2] = *(const uint32_t*)(p + 8);
                af[t][3] = *(const uint32_t*)(p + 8 * A_STRIDEH + 8);
            }
            #pragma unroll
            for (int j = 0; j < 8; j++) {
                uint2 v = *(const uint2*)(Bs + kk * (4 * BROW_BYTES) + tig * BROW_BYTES
                                          + (wn * 64 + j * 8 + g) * 8);
                bf[j][0] = v.x;
                bf[j][1] = v.y;
            }
            #pragma unroll
            for (int t = 0; t < 4; t++)
                #pragma unroll
                for (int j = 0; j < 8; j++)
                    mma16(acc[t][j], af[t], bf[j]);
        }

        // ---- convert + store prefetched A into the other stage
        if (cg < NCG - 1) {
            __half* adst = (__half*)(smp + SM_STAGE + (s ^ 1) * STAGE_BYTES);
            #pragma unroll
            for (int i = 0; i < 4; i++) {
                int u = tid + i * 256;
                int row = u >> 2, q = u & 3;
                uint4 h;
                h.x = pack_h2(apf[2 * i].x,     apf[2 * i].y);
                h.y = pack_h2(apf[2 * i].z,     apf[2 * i].w);
                h.z = pack_h2(apf[2 * i + 1].x, apf[2 * i + 1].y);
                h.w = pack_h2(apf[2 * i + 1].z, apf[2 * i + 1].w);
                *(uint4*)(adst + row * A_STRIDEH + q * 8) = h;
            }
        }

        // ---- epilogue at the end of each n-block (overlaps in-flight fill)
        if ((cg & 15) == 15) {
            const int nb = cg >> 4;
            const float* bm = b_merge + dir * ODIM_ + nb * 128 + wn * 64;
            float2 bb[8];
            #pragma unroll
            for (int j = 0; j < 8; j++) bb[j] = *(const float2*)(bm + j * 8 + 2 * tig);
            #pragma unroll
            for (int t = 0; t < 4; t++) {
                #pragma unroll
                for (int h = 0; h < 2; h++) {
                    int r = wm * 64 + t * 16 + h * 8 + g;
                    int tok = rowTok[r];
                    if (tok >= 0) {
                        float* op = out + (size_t)tok * ODIM_ + nb * 128 + wn * 64;
                        #pragma unroll
                        for (int j = 0; j < 8; j++) {
                            float y0 = acc[t][j][h * 2 + 0] + bb[j].x;
                            float y1 = acc[t][j][h * 2 + 1] + bb[j].y;
                            float2 v;
                            v.x = y0 > 0.f ? y0 : alpha * y0;
                            v.y = y1 > 0.f ? y1 : alpha * y1;
                            *(float2*)(op + j * 8 + 2 * tig) = v;
                        }
                    }
                }
            }
            #pragma unroll
            for (int t = 0; t < 4; t++)
                #pragma unroll
                for (int j = 0; j < 8; j++)
                    #pragma unroll
                    for (int q = 0; q < 4; q++) acc[t][j][q] = 0.f;
        }

        CP_WAIT0();
        __syncthreads();
    }
}

// ---------------------------------------------------------------- launch
extern "C" void kernel_launch(void* const* d_in, const int* in_sizes, int n_in,
                              void* d_out, int out_size) {
    const float* last  = (const float*)d_in[0];
    const float* W     = (const float*)d_in[1];
    const float* bm    = (const float*)d_in[2];
    const float* am    = (const float*)d_in[3];
    const int*   cl    = (const int*)d_in[4];
    const int*   cr    = (const int*)d_in[5];
    const int*   vec   = (const int*)d_in[6];
    const int*   drev  = (const int*)d_in[7];
    const int*   dmap  = (const int*)d_in[8];
    float*       out   = (float*)d_out;

    (void)in_sizes; (void)n_in; (void)out_size;

    static bool attr_done = false;
    if (!attr_done) {
        cudaFuncSetAttribute(k_gemm, cudaFuncAttributeMaxDynamicSharedMemorySize, SMEM_DYN);
        attr_done = true;
    }

    k_prep<<<384, 256>>>(W);
    k_bucket<<<NTOK / 256, 256>>>(cl, cr, vec, drev, dmap);
    k_gemm<<<MAXTILES, 256, SMEM_DYN>>>(last, bm, am, out);
}

// round 14
// speedup vs baseline: 1.4086x; 1.1103x over previous
#include <cuda_runtime.h>
#include <cuda_fp16.h>
#include <cstdint>

// ---------------------------------------------------------------- problem dims
#define NDIRS   6
#define IDIM_   256
#define ODIM_   512
#define LSEQ    4096
#define NCHN    8192
#define NTOK    32768
#define KTOT    512
#define MTILE   128
#define KC      32                    // K per smem chunk
#define NKCH    16                    // K chunks per unit (K=512)
#define NNB     4                     // n-blocks of 128
#define NCG     (NNB * NKCH)          // 64 B-blocks per dir
#define MAXTILES (NTOK / MTILE + NDIRS)   // 262
#define NUNITS  (MAXTILES * NNB)      // 1048

// B packed block (fp16): per (dir, cg): 2 kk16-groups * 4 tig * 1056B rows
#define BROW_BYTES   1056             // 128 cols * 8B + 32B pad
#define BBLK_BYTES   (2 * 4 * BROW_BYTES)   // 8448
#define BUNITS       (BBLK_BYTES / 16)      // 528 16B units

// A smem (fp16): 128 rows * 40 halfs (80B stride; 64B data)
#define A_STRIDEH    40
#define A_BYTES      (128 * A_STRIDEH * 2)  // 10240
#define STAGE_BYTES  (A_BYTES + BBLK_BYTES) // 18688
#define SM_ROWTOK    0
#define SM_ROWS0     512
#define SM_ROWS1     1024
#define SM_STAGE     2048
#define SMEM_DYN     (SM_STAGE + 2 * STAGE_BYTES)   // 39424

// ---------------------------------------------------------------- device scratch
__device__ __align__(16) char g_WpH[NDIRS * NCG * BBLK_BYTES];  // fp16 fragment-packed W
__device__ int   g_count[NDIRS];
__device__ int2  g_bucket[NDIRS * NTOK];

// ---------------------------------------------------------------- helpers
__device__ __forceinline__ uint32_t smem_u32(const void* p) {
    uint32_t a;
    asm("{ .reg .u64 t; cvta.to.shared.u64 t, %1; cvt.u32.u64 %0, t; }" : "=r"(a) : "l"(p));
    return a;
}
__device__ __forceinline__ void cp16(uint32_t dst, const void* src) {
    asm volatile("cp.async.cg.shared.global [%0], [%1], 16;\n" :: "r"(dst), "l"(src) : "memory");
}
#define CP_COMMIT() asm volatile("cp.async.commit_group;\n" ::: "memory")
#define CP_WAIT0()  asm volatile("cp.async.wait_group 0;\n" ::: "memory")

__device__ __forceinline__ void mma16(float* c, const uint32_t* a, const uint32_t* b) {
    asm volatile(
        "mma.sync.aligned.m16n8k16.row.col.f32.f16.f16.f32 "
        "{%0,%1,%2,%3}, {%4,%5,%6,%7}, {%8,%9}, {%0,%1,%2,%3};\n"
        : "+f"(c[0]), "+f"(c[1]), "+f"(c[2]), "+f"(c[3])
        : "r"(a[0]), "r"(a[1]), "r"(a[2]), "r"(a[3]), "r"(b[0]), "r"(b[1]));
}

__device__ __forceinline__ uint32_t pack_h2(float a, float b) {
    __half2 h = __floats2half2_rn(a, b);
    return *(uint32_t*)&h;
}

// ---------------------------------------------------------------- K0: pack W -> fp16 fragment layout
__global__ void k_prep(const float* __restrict__ W) {
    if (blockIdx.x == 0 && threadIdx.x < NDIRS) g_count[threadIdx.x] = 0;
    int linear = blockIdx.x * 256 + threadIdx.x;
    int col = linear & 127;
    int kk  = (linear >> 7) & 1;
    int ch  = (linear >> 8) & 15;
    int nbd = linear >> 12;                      // d*4 + nb, 0..23

    const float* src = W + ((size_t)nbd * 128 + col) * KTOT + ch * KC + kk * 16;
    float x[16];
    #pragma unroll
    for (int i = 0; i < 4; i++) {
        float4 v = *(const float4*)(src + i * 4);
        x[i * 4 + 0] = v.x; x[i * 4 + 1] = v.y; x[i * 4 + 2] = v.z; x[i * 4 + 3] = v.w;
    }
    char* dst = g_WpH + (size_t)(nbd * 16 + ch) * BBLK_BYTES + kk * (4 * BROW_BYTES) + col * 8;
    #pragma unroll
    for (int t = 0; t < 4; t++) {
        uint2 u;
        u.x = pack_h2(x[2 * t],     x[2 * t + 1]);
        u.y = pack_h2(x[8 + 2 * t], x[9 + 2 * t]);
        *(uint2*)(dst + t * BROW_BYTES) = u;
    }
}

// ---------------------------------------------------------------- K1: bucket tokens by dir
__global__ void k_bucket(const int* __restrict__ child_l, const int* __restrict__ child_r,
                         const int* __restrict__ vec, const int* __restrict__ drev,
                         const int* __restrict__ dmap) {
    int t = blockIdx.x * blockDim.x + threadIdx.x;
    int l = t & (LSEQ - 1);
    int v = vec[t];
    int dir = dmap[v];
    int d = drev[v];
    int cl = child_l[l], cr = child_r[l];
    int c0 = d ? cr : cl;
    int c1 = d ? cl : cr;
    int payload = c0 | (c1 << 16);
    int lane = threadIdx.x & 31;

    #pragma unroll
    for (int dd = 0; dd < NDIRS; dd++) {
        unsigned mask = __ballot_sync(0xFFFFFFFFu, dir == dd);
        if (dir == dd) {
            int leader = __ffs(mask) - 1;
            int base = 0;
            if (lane == leader) base = atomicAdd(&g_count[dd], __popc(mask));
            base = __shfl_sync(mask, base, leader);
            int pos = base + __popc(mask & ((1u << lane) - 1u));
            g_bucket[dd * NTOK + pos] = make_int2(t, payload);
        }
    }
}

// ---------------------------------------------------------------- K2: bucketed fp16 GEMM
// Unit = (dir-tile, nb): 128x128x512.  Grid = 1048 units, 128 threads, occ 2.
// Warp tile m64 x n64: wm = wid&1, wn = wid>>1.
__global__ void __launch_bounds__(128, 2) k_gemm(
    const float* __restrict__ last,
    const float* __restrict__ b_merge,
    const float* __restrict__ alpha_merge,
    float* __restrict__ out)
{
    extern __shared__ char smp[];
    const uint32_t sbase = smem_u32(smp);

    const int tid = threadIdx.x;
    const int wid = tid >> 5;
    const int lid = tid & 31;
    const int wm = wid & 1;       // M half (64 rows)
    const int wn = wid >> 1;      // N half (64 cols)
    const int g   = lid >> 2;     // group (0..7)
    const int tig = lid & 3;      // thread-in-group (0..3)

    // ---- map CTA -> (dir, tile, nb)
    const int nb = blockIdx.x & 3;
    const int T  = blockIdx.x >> 2;
    int dir = -1, tile = 0;
    {
        int acc0 = 0;
        #pragma unroll
        for (int d = 0; d < NDIRS; d++) {
            int nt = (g_count[d] + MTILE - 1) >> 7;
            if (dir < 0 && T < acc0 + nt) { dir = d; tile = T - acc0; }
            acc0 += nt;
        }
    }
    if (dir < 0) return;
    const int count = g_count[dir];

    // ---- row metadata (128 threads cover 128 rows)
    {
        int idx = tile * MTILE + tid;
        int2 e = (idx < count) ? g_bucket[dir * NTOK + idx] : make_int2(0, 0);
        ((int*)(smp + SM_ROWTOK))[tid] = (idx < count) ? e.x : -1;
        int c0 = e.y & 0xFFFF;
        int c1 = (e.y >> 16) & 0xFFFF;
        int bb = e.x >> 12;                 // token / LSEQ
        ((int*)(smp + SM_ROWS0))[tid] = bb * NCHN + c0;
        ((int*)(smp + SM_ROWS1))[tid] = bb * NCHN + c1;
    }
    const float alpha = alpha_merge[dir];
    __syncthreads();

    const int* rs0 = (const int*)(smp + SM_ROWS0);
    const int* rs1 = (const int*)(smp + SM_ROWS1);
    const int* rowTok = (const int*)(smp + SM_ROWTOK);
    const char* __restrict__ WpB = g_WpH + (size_t)(dir * NCG + nb * NKCH) * BBLK_BYTES;

    float acc[4][8][4];
    #pragma unroll
    for (int t = 0; t < 4; t++)
        #pragma unroll
        for (int j = 0; j < 8; j++)
            #pragma unroll
            for (int q = 0; q < 4; q++) acc[t][j][q] = 0.f;

    // ---- prologue: fill chunk 0 into stage 0
    {
        uint32_t bdst = sbase + SM_STAGE + A_BYTES;
        const char* bsrc = WpB;
        #pragma unroll
        for (int i = 0; i < 4; i++) { int u = tid + i * 128; cp16(bdst + u * 16, bsrc + u * 16); }
        if (tid < BUNITS - 512) { int u = tid + 512; cp16(bdst + u * 16, bsrc + u * 16); }
        CP_COMMIT();
        __half* adst = (__half*)(smp + SM_STAGE);
        #pragma unroll
        for (int i = 0; i < 4; i++) {
            int u = tid + i * 128;            // 512 units: 128 rows x 4 eight-half groups
            int row = u >> 2, q = u & 3;
            const float* ap = last + (size_t)rs0[row] * IDIM_ + q * 8;
            float4 v0 = *(const float4*)(ap);
            float4 v1 = *(const float4*)(ap + 4);
            uint4 h;
            h.x = pack_h2(v0.x, v0.y); h.y = pack_h2(v0.z, v0.w);
            h.z = pack_h2(v1.x, v1.y); h.w = pack_h2(v1.z, v1.w);
            *(uint4*)(adst + row * A_STRIDEH + q * 8) = h;
        }
        CP_WAIT0();
        __syncthreads();
    }

    for (int c = 0; c < NKCH; c++) {
        const int s = c & 1;
        float4 apf[8];

        // ---- prefetch chunk c+1: B via cp.async, A via LDG (held in regs)
        if (c < NKCH - 1) {
            const int c2 = c + 1;
            uint32_t bdst = sbase + SM_STAGE + (s ^ 1) * STAGE_BYTES + A_BYTES;
            const char* bsrc = WpB + (size_t)c2 * BBLK_BYTES;
            #pragma unroll
            for (int i = 0; i < 4; i++) { int u = tid + i * 128; cp16(bdst + u * 16, bsrc + u * 16); }
            if (tid < BUNITS - 512) { int u = tid + 512; cp16(bdst + u * 16, bsrc + u * 16); }
            CP_COMMIT();
            const int* rs = (c2 < 8) ? rs0 : rs1;
            const int koff = (c2 & 7) * KC;
            #pragma unroll
            for (int i = 0; i < 4; i++) {
                int u = tid + i * 128;
                int row = u >> 2, q = u & 3;
                const float* ap = last + (size_t)rs[row] * IDIM_ + koff + q * 8;
                apf[2 * i]     = *(const float4*)(ap);
                apf[2 * i + 1] = *(const float4*)(ap + 4);
            }
        }

        // ---- compute chunk c from stage s (2 k16-groups x 32 MMA)
        const __half* As = (const __half*)(smp + SM_STAGE + s * STAGE_BYTES);
        const char*   Bs = smp + SM_STAGE + s * STAGE_BYTES + A_BYTES;
        #pragma unroll
        for (int kk = 0; kk < 2; kk++) {
            uint32_t af[4][4];
            uint32_t bf[8][2];
            #pragma unroll
            for (int t = 0; t < 4; t++) {
                const __half* p = As + (wm * 64 + t * 16 + g) * A_STRIDEH + kk * 16 + 2 * tig;
                af[t][0] = *(const uint32_t*)(p);
                af[t][1] = *(const uint32_t*)(p + 8 * A_STRIDEH);
                af[t][2] = *(const uint32_t*)(p + 8);
                af[t][3] = *(const uint32_t*)(p + 8 * A_STRIDEH + 8);
            }
            #pragma unroll
            for (int j = 0; j < 8; j++) {
                uint2 v = *(const uint2*)(Bs + kk * (4 * BROW_BYTES) + tig * BROW_BYTES
                                          + (wn * 64 + j * 8 + g) * 8);
                bf[j][0] = v.x;
                bf[j][1] = v.y;
            }
            #pragma unroll
            for (int t = 0; t < 4; t++)
                #pragma unroll
                for (int j = 0; j < 8; j++)
                    mma16(acc[t][j], af[t], bf[j]);
        }

        // ---- convert + store prefetched A into the other stage
        if (c < NKCH - 1) {
            __half* adst = (__half*)(smp + SM_STAGE + (s ^ 1) * STAGE_BYTES);
            #pragma unroll
            for (int i = 0; i < 4; i++) {
                int u = tid + i * 128;
                int row = u >> 2, q = u & 3;
                uint4 h;
                h.x = pack_h2(apf[2 * i].x,     apf[2 * i].y);
                h.y = pack_h2(apf[2 * i].z,     apf[2 * i].w);
                h.z = pack_h2(apf[2 * i + 1].x, apf[2 * i + 1].y);
                h.w = pack_h2(apf[2 * i + 1].z, apf[2 * i + 1].w);
                *(uint4*)(adst + row * A_STRIDEH + q * 8) = h;
            }
            CP_WAIT0();
            __syncthreads();
        }
    }

    // ---- epilogue
    {
        const float* bm = b_merge + dir * ODIM_ + nb * 128 + wn * 64;
        float2 bb[8];
        #pragma unroll
        for (int j = 0; j < 8; j++) bb[j] = *(const float2*)(bm + j * 8 + 2 * tig);
        #pragma unroll
        for (int t = 0; t < 4; t++) {
            #pragma unroll
            for (int h = 0; h < 2; h++) {
                int r = wm * 64 + t * 16 + h * 8 + g;
                int tok = rowTok[r];
                if (tok >= 0) {
                    float* op = out + (size_t)tok * ODIM_ + nb * 128 + wn * 64;
                    #pragma unroll
                    for (int j = 0; j < 8; j++) {
                        float y0 = acc[t][j][h * 2 + 0] + bb[j].x;
                        float y1 = acc[t][j][h * 2 + 1] + bb[j].y;
                        float2 v;
                        v.x = y0 > 0.f ? y0 : alpha * y0;
                        v.y = y1 > 0.f ? y1 : alpha * y1;
                        *(float2*)(op + j * 8 + 2 * tig) = v;
                    }
                }
            }
        }
    }
}

// ---------------------------------------------------------------- launch
extern "C" void kernel_launch(void* const* d_in, const int* in_sizes, int n_in,
                              void* d_out, int out_size) {
    const float* last  = (const float*)d_in[0];
    const float* W     = (const float*)d_in[1];
    const float* bm    = (const float*)d_in[2];
    const float* am    = (const float*)d_in[3];
    const int*   cl    = (const int*)d_in[4];
    const int*   cr    = (const int*)d_in[5];
    const int*   vec   = (const int*)d_in[6];
    const int*   drev  = (const int*)d_in[7];
    const int*   dmap  = (const int*)d_in[8];
    float*       out   = (float*)d_out;

    (void)in_sizes; (void)n_in; (void)out_size;

    static bool attr_done = false;
    if (!attr_done) {
        cudaFuncSetAttribute(k_gemm, cudaFuncAttributeMaxDynamicSharedMemorySize, SMEM_DYN);
        attr_done = true;
    }

    k_prep<<<384, 256>>>(W);
    k_bucket<<<NTOK / 256, 256>>>(cl, cr, vec, drev, dmap);
    k_gemm<<<NUNITS, 128, SMEM_DYN>>>(last, bm, am, out);
}

// round 16
// speedup vs baseline: 1.5640x; 1.1103x over previous
#include <cuda_runtime.h>
#include <cuda_fp16.h>
#include <cstdint>

// ---------------------------------------------------------------- problem dims
#define NDIRS   6
#define IDIM_   256
#define ODIM_   512
#define LSEQ    4096
#define NCHN    8192
#define NTOK    32768
#define KTOT    512
#define MTILE   128
#define KC      64                    // K per smem chunk
#define NKCH    8                     // K chunks per n-block (512/64)
#define NNB     4                     // n-blocks of 128
#define NCG     (NNB * NKCH)          // 32 global chunks
#define MAXTILES (NTOK / MTILE + NDIRS)   // 262

// B packed (fp16), KC32 granule: 2 kk16-groups * 4 tig * 1056B rows = 8448B
#define BROW_BYTES   1056             // 128 cols * 8B + 32B pad
#define BBLK_BYTES   8448             // one KC32 granule
#define BCHUNK_BYTES (2 * BBLK_BYTES) // 16896 per KC64 chunk (contiguous)
#define BUNITS       (BCHUNK_BYTES / 16)    // 1056 16B units

// A smem (fp16): 128 rows * 72 halfs (144B stride; 128B data)
#define A_STRIDEH    72
#define A_BYTES      (128 * A_STRIDEH * 2)  // 18432
#define STAGE_BYTES  (A_BYTES + BCHUNK_BYTES) // 35328
#define SM_ROWTOK    0
#define SM_ROWS0     512
#define SM_ROWS1     1024
#define SM_STAGE     2048
#define SMEM_DYN     (SM_STAGE + 2 * STAGE_BYTES)   // 72704

// ---------------------------------------------------------------- device scratch
__device__ __align__(16) char g_WpH[NDIRS * 16 * NNB * BBLK_BYTES];  // fp16 fragment-packed W
__device__ int   g_count[NDIRS];
__device__ int2  g_bucket[NDIRS * NTOK];

// ---------------------------------------------------------------- helpers
__device__ __forceinline__ uint32_t smem_u32(const void* p) {
    uint32_t a;
    asm("{ .reg .u64 t; cvta.to.shared.u64 t, %1; cvt.u32.u64 %0, t; }" : "=r"(a) : "l"(p));
    return a;
}
__device__ __forceinline__ void cp16(uint32_t dst, const void* src) {
    asm volatile("cp.async.cg.shared.global [%0], [%1], 16;\n" :: "r"(dst), "l"(src) : "memory");
}
#define CP_COMMIT() asm volatile("cp.async.commit_group;\n" ::: "memory")
#define CP_WAIT0()  asm volatile("cp.async.wait_group 0;\n" ::: "memory")

__device__ __forceinline__ void mma16(float* c, const uint32_t* a, const uint32_t* b) {
    asm volatile(
        "mma.sync.aligned.m16n8k16.row.col.f32.f16.f16.f32 "
        "{%0,%1,%2,%3}, {%4,%5,%6,%7}, {%8,%9}, {%0,%1,%2,%3};\n"
        : "+f"(c[0]), "+f"(c[1]), "+f"(c[2]), "+f"(c[3])
        : "r"(a[0]), "r"(a[1]), "r"(a[2]), "r"(a[3]), "r"(b[0]), "r"(b[1]));
}

__device__ __forceinline__ uint32_t pack_h2(float a, float b) {
    __half2 h = __floats2half2_rn(a, b);
    return *(uint32_t*)&h;
}

// ---------------------------------------------------------------- K0: pack W -> fp16 fragment layout
// 384 blocks (nbd*16+ch), 256 threads. Coalesced read -> smem -> coalesced packed write.
__global__ void k_prep(const float* __restrict__ W) {
    int b = blockIdx.x;
    int ch  = b & 15;
    int nbd = b >> 4;                          // d*4 + nb, 0..23
    if (b == 0 && threadIdx.x < NDIRS) g_count[threadIdx.x] = 0;

    __shared__ float tile[128][33];            // [col][k within 32]
    int tid = threadIdx.x;

    // coalesced read: 1024 float4 units; unit u: col = u>>3, kq = u&7
    #pragma unroll
    for (int i = 0; i < 4; i++) {
        int u = tid + i * 256;
        int col = u >> 3, kq = u & 7;
        float4 v = *(const float4*)(W + ((size_t)nbd * 128 + col) * KTOT + ch * 32 + kq * 4);
        tile[col][kq * 4 + 0] = v.x;
        tile[col][kq * 4 + 1] = v.y;
        tile[col][kq * 4 + 2] = v.z;
        tile[col][kq * 4 + 3] = v.w;
    }
    __syncthreads();

    // packed write: 1056 8B units (kk 0..1, tg 0..3, cc 0..131 incl pad)
    char* dst = g_WpH + (size_t)b * BBLK_BYTES;
    #pragma unroll
    for (int i = 0; i < 5; i++) {
        int u = tid + i * 256;
        if (u >= 1056) break;
        int kk = u / 528;
        int r  = u - kk * 528;
        int tg = r / 132;
        int cc = r - tg * 132;
        if (cc < 128) {
            uint2 v;
            v.x = pack_h2(tile[cc][kk * 16 + 2 * tg],     tile[cc][kk * 16 + 2 * tg + 1]);
            v.y = pack_h2(tile[cc][kk * 16 + 8 + 2 * tg], tile[cc][kk * 16 + 9 + 2 * tg]);
            *(uint2*)(dst + kk * (4 * BROW_BYTES) + tg * BROW_BYTES + cc * 8) = v;
        }
    }
}

// ---------------------------------------------------------------- K1: bucket tokens by dir
__global__ void k_bucket(const int* __restrict__ child_l, const int* __restrict__ child_r,
                         const int* __restrict__ vec, const int* __restrict__ drev,
                         const int* __restrict__ dmap) {
    int t = blockIdx.x * blockDim.x + threadIdx.x;
    int l = t & (LSEQ - 1);
    int v = vec[t];
    int dir = dmap[v];
    int d = drev[v];
    int cl = child_l[l], cr = child_r[l];
    int c0 = d ? cr : cl;
    int c1 = d ? cl : cr;
    int payload = c0 | (c1 << 16);
    int lane = threadIdx.x & 31;

    #pragma unroll
    for (int dd = 0; dd < NDIRS; dd++) {
        unsigned mask = __ballot_sync(0xFFFFFFFFu, dir == dd);
        if (dir == dd) {
            int leader = __ffs(mask) - 1;
            int base = 0;
            if (lane == leader) base = atomicAdd(&g_count[dd], __popc(mask));
            base = __shfl_sync(mask, base, leader);
            int pos = base + __popc(mask & ((1u << lane) - 1u));
            g_bucket[dd * NTOK + pos] = make_int2(t, payload);
        }
    }
}

// ---------------------------------------------------------------- K2: bucketed fp16 GEMM, KC=64
// 262 CTAs, 128 threads (4 warps, m64 x n64), occ 2; global chunk stream cg=0..31.
__global__ void __launch_bounds__(128, 2) k_gemm(
    const float* __restrict__ last,
    const float* __restrict__ b_merge,
    const float* __restrict__ alpha_merge,
    float* __restrict__ out)
{
    extern __shared__ char smp[];
    const uint32_t sbase = smem_u32(smp);

    const int tid = threadIdx.x;
    const int wid = tid >> 5;
    const int lid = tid & 31;
    const int wm = wid & 1;       // M half (64 rows)
    const int wn = wid >> 1;      // N half (64 cols)
    const int g   = lid >> 2;     // group (0..7)
    const int tig = lid & 3;      // thread-in-group (0..3)

    // ---- map CTA -> (dir, tile)
    int dir = -1, tile = 0;
    {
        int acc0 = 0;
        #pragma unroll
        for (int d = 0; d < NDIRS; d++) {
            int nt = (g_count[d] + MTILE - 1) >> 7;
            if (dir < 0 && (int)blockIdx.x < acc0 + nt) { dir = d; tile = blockIdx.x - acc0; }
            acc0 += nt;
        }
    }
    if (dir < 0) return;
    const int count = g_count[dir];

    // ---- row metadata
    {
        int idx = tile * MTILE + tid;
        int2 e = (idx < count) ? g_bucket[dir * NTOK + idx] : make_int2(0, 0);
        ((int*)(smp + SM_ROWTOK))[tid] = (idx < count) ? e.x : -1;
        int c0 = e.y & 0xFFFF;
        int c1 = (e.y >> 16) & 0xFFFF;
        int bb = e.x >> 12;
        ((int*)(smp + SM_ROWS0))[tid] = bb * NCHN + c0;
        ((int*)(smp + SM_ROWS1))[tid] = bb * NCHN + c1;
    }
    const float alpha = alpha_merge[dir];
    __syncthreads();

    const int* rs0 = (const int*)(smp + SM_ROWS0);
    const int* rs1 = (const int*)(smp + SM_ROWS1);
    const int* rowTok = (const int*)(smp + SM_ROWTOK);
    const char* __restrict__ WpD = g_WpH + (size_t)(dir * 64) * BBLK_BYTES;

    float acc[4][8][4];
    #pragma unroll
    for (int t = 0; t < 4; t++)
        #pragma unroll
        for (int j = 0; j < 8; j++)
            #pragma unroll
            for (int q = 0; q < 4; q++) acc[t][j][q] = 0.f;

    // ---- prologue: fill chunk 0 into stage 0
    {
        uint32_t bdst = sbase + SM_STAGE + A_BYTES;
        const char* bsrc = WpD;                 // chunk 0 = KC32 blocks 0,1 (contiguous)
        #pragma unroll
        for (int i = 0; i < 8; i++) { int u = tid + i * 128; cp16(bdst + u * 16, bsrc + u * 16); }
        if (tid < BUNITS - 1024) { int u = tid + 1024; cp16(bdst + u * 16, bsrc + u * 16); }
        CP_COMMIT();
        __half* adst = (__half*)(smp + SM_STAGE);
        #pragma unroll
        for (int i = 0; i < 16; i++) {
            int u = tid + i * 128;              // 2048 float4 units: 128 rows x 16
            int row = u >> 4, q = u & 15;
            float4 v = *(const float4*)(last + (size_t)rs0[row] * IDIM_ + q * 4);
            uint2 h;
            h.x = pack_h2(v.x, v.y); h.y = pack_h2(v.z, v.w);
            *(uint2*)(adst + row * A_STRIDEH + q * 4) = h;
        }
        CP_WAIT0();
        __syncthreads();
    }

    for (int cg = 0; cg < NCG; cg++) {
        const int s = cg & 1;
        float4 apf[8];
        const int c2 = cg + 1;
        const int* rs2 = ((c2 & 7) < 4) ? rs0 : rs1;
        const int koff2 = (c2 & 3) * KC;
        __half* adst = (__half*)(smp + SM_STAGE + (s ^ 1) * STAGE_BYTES);

        // ---- prefetch B(cg+1) + A(cg+1) half 0
        if (cg < NCG - 1) {
            uint32_t bdst = sbase + SM_STAGE + (s ^ 1) * STAGE_BYTES + A_BYTES;
            const char* bsrc = WpD + (size_t)(2 * c2) * BBLK_BYTES;
            #pragma unroll
            for (int i = 0; i < 8; i++) { int u = tid + i * 128; cp16(bdst + u * 16, bsrc + u * 16); }
            if (tid < BUNITS - 1024) { int u = tid + 1024; cp16(bdst + u * 16, bsrc + u * 16); }
            CP_COMMIT();
            #pragma unroll
            for (int i = 0; i < 8; i++) {
                int u = tid + i * 128;          // 1024 float4: 128 rows x 8 (k 0..31)
                int row = u >> 3, q = u & 7;
                apf[i] = *(const float4*)(last + (size_t)rs2[row] * IDIM_ + koff2 + q * 4);
            }
        }

        const __half* As = (const __half*)(smp + SM_STAGE + s * STAGE_BYTES);
        const char*   Bs = smp + SM_STAGE + s * STAGE_BYTES + A_BYTES;

        // ---- compute kk = 0,1
        #pragma unroll
        for (int kk = 0; kk < 2; kk++) {
            uint32_t af[4][4], bf[8][2];
            #pragma unroll
            for (int t = 0; t < 4; t++) {
                const __half* p = As + (wm * 64 + t * 16 + g) * A_STRIDEH + kk * 16 + 2 * tig;
                af[t][0] = *(const uint32_t*)(p);
                af[t][1] = *(const uint32_t*)(p + 8 * A_STRIDEH);
                af[t][2] = *(const uint32_t*)(p + 8);
                af[t][3] = *(const uint32_t*)(p + 8 * A_STRIDEH + 8);
            }
            #pragma unroll
            for (int j = 0; j < 8; j++) {
                uint2 v = *(const uint2*)(Bs + kk * (4 * BROW_BYTES) + tig * BROW_BYTES
                                          + (wn * 64 + j * 8 + g) * 8);
                bf[j][0] = v.x; bf[j][1] = v.y;
            }
            #pragma unroll
            for (int t = 0; t < 4; t++)
                #pragma unroll
                for (int j = 0; j < 8; j++)
                    mma16(acc[t][j], af[t], bf[j]);
        }

        // ---- store A half0, load A half1
        if (cg < NCG - 1) {
            #pragma unroll
            for (int i = 0; i < 8; i++) {
                int u = tid + i * 128;
                int row = u >> 3, q = u & 7;
                uint2 h;
                h.x = pack_h2(apf[i].x, apf[i].y); h.y = pack_h2(apf[i].z, apf[i].w);
                *(uint2*)(adst + row * A_STRIDEH + q * 4) = h;
            }
            #pragma unroll
            for (int i = 0; i < 8; i++) {
                int u = tid + i * 128;          // k 32..63
                int row = u >> 3, q = u & 7;
                apf[i] = *(const float4*)(last + (size_t)rs2[row] * IDIM_ + koff2 + 32 + q * 4);
            }
        }

        // ---- compute kk = 2,3  (second KC32 granule of this chunk)
        #pragma unroll
        for (int kk = 2; kk < 4; kk++) {
            uint32_t af[4][4], bf[8][2];
            #pragma unroll
            for (int t = 0; t < 4; t++) {
                const __half* p = As + (wm * 64 + t * 16 + g) * A_STRIDEH + kk * 16 + 2 * tig;
                af[t][0] = *(const uint32_t*)(p);
                af[t][1] = *(const uint32_t*)(p + 8 * A_STRIDEH);
                af[t][2] = *(const uint32_t*)(p + 8);
                af[t][3] = *(const uint32_t*)(p + 8 * A_STRIDEH + 8);
            }
            #pragma unroll
            for (int j = 0; j < 8; j++) {
                uint2 v = *(const uint2*)(Bs + BBLK_BYTES + (kk - 2) * (4 * BROW_BYTES)
                                          + tig * BROW_BYTES + (wn * 64 + j * 8 + g) * 8);
                bf[j][0] = v.x; bf[j][1] = v.y;
            }
            #pragma unroll
            for (int t = 0; t < 4; t++)
                #pragma unroll
                for (int j = 0; j < 8; j++)
                    mma16(acc[t][j], af[t], bf[j]);
        }

        // ---- store A half1
        if (cg < NCG - 1) {
            #pragma unroll
            for (int i = 0; i < 8; i++) {
                int u = tid + i * 128;
                int row = u >> 3, q = u & 7;
                uint2 h;
                h.x = pack_h2(apf[i].x, apf[i].y); h.y = pack_h2(apf[i].z, apf[i].w);
                *(uint2*)(adst + row * A_STRIDEH + 32 + q * 4) = h;
            }
        }

        // ---- epilogue at the end of each n-block (hides in-flight fill)
        if ((cg & 7) == 7) {
            const int nb = cg >> 3;
            const float* bm = b_merge + dir * ODIM_ + nb * 128 + wn * 64;
            float2 bb[8];
            #pragma unroll
            for (int j = 0; j < 8; j++) bb[j] = *(const float2*)(bm + j * 8 + 2 * tig);
            #pragma unroll
            for (int t = 0; t < 4; t++) {
                #pragma unroll
                for (int h = 0; h < 2; h++) {
                    int r = wm * 64 + t * 16 + h * 8 + g;
                    int tok = rowTok[r];
                    if (tok >= 0) {
                        float* op = out + (size_t)tok * ODIM_ + nb * 128 + wn * 64;
                        #pragma unroll
                        for (int j = 0; j < 8; j++) {
                            float y0 = acc[t][j][h * 2 + 0] + bb[j].x;
                            float y1 = acc[t][j][h * 2 + 1] + bb[j].y;
                            float2 v;
                            v.x = y0 > 0.f ? y0 : alpha * y0;
                            v.y = y1 > 0.f ? y1 : alpha * y1;
                            *(float2*)(op + j * 8 + 2 * tig) = v;
                        }
                    }
                }
            }
            #pragma unroll
            for (int t = 0; t < 4; t++)
                #pragma unroll
                for (int j = 0; j < 8; j++)
                    #pragma unroll
                    for (int q = 0; q < 4; q++) acc[t][j][q] = 0.f;
        }

        CP_WAIT0();
        __syncthreads();
    }
}

// ---------------------------------------------------------------- launch
extern "C" void kernel_launch(void* const* d_in, const int* in_sizes, int n_in,
                              void* d_out, int out_size) {
    const float* last  = (const float*)d_in[0];
    const float* W     = (const float*)d_in[1];
    const float* bm    = (const float*)d_in[2];
    const float* am    = (const float*)d_in[3];
    const int*   cl    = (const int*)d_in[4];
    const int*   cr    = (const int*)d_in[5];
    const int*   vec   = (const int*)d_in[6];
    const int*   drev  = (const int*)d_in[7];
    const int*   dmap  = (const int*)d_in[8];
    float*       out   = (float*)d_out;

    (void)in_sizes; (void)n_in; (void)out_size;

    static bool attr_done = false;
    if (!attr_done) {
        cudaFuncSetAttribute(k_gemm, cudaFuncAttributeMaxDynamicSharedMemorySize, SMEM_DYN);
        attr_done = true;
    }

    k_prep<<<384, 256>>>(W);
    k_bucket<<<NTOK / 256, 256>>>(cl, cr, vec, drev, dmap);
    k_gemm<<<MAXTILES, 128, SMEM_DYN>>>(last, bm, am, out);
}